// round 15
// baseline (speedup 1.0000x reference)
#include <cuda_runtime.h>
#include <math.h>

// Problem constants
#define B_   16
#define C_   256
#define HH_  64
#define WW_  64
#define N_   4096      // HH*WW
#define K_   16
#define H_   4
#define U_   4
#define R_   23
#define DV_  64
#define EPS_ 1e-3f

#define WSTRIDE 66     // f-stride of W-hat table (float2 units)
#define FIDX(i) ((i) + ((i) >> 3))   // padded FFT line index (what_kernel only)
#define FLINE 144

// Scratch (device globals; no allocation allowed)
__device__ float  g_wfold[384 * 256];
__device__ float  g_bias[384];
__device__ float  g_proj[(size_t)B_ * 384 * N_];          // rows 0-63 q, 64-127 k, 128-383 v
__device__ float  g_LcPart[(size_t)B_ * 32 * 1024];
__device__ float  g_Lc[B_ * K_ * DV_];                    // [b][k][dv]
__device__ float2 g_tw[64];                               // fwd twiddles W_128^j
__device__ float2 g_What2[1473 * WSTRIDE];                // [row=k*92+u*23+dy][f] (+1 pad row)
__device__ float2 g_Rhat[(size_t)262144 * 65];            // [(b*64+dv)*4+u][y][f]

// ---- packed fp32x2 helpers --------------------------------------------------
__device__ __forceinline__ unsigned long long pk2(float lo, float hi) {
    unsigned long long r;
    asm("mov.b64 %0, {%1, %2};" : "=l"(r) : "f"(lo), "f"(hi));
    return r;
}
__device__ __forceinline__ void ffma2(unsigned long long& d, unsigned long long a,
                                      unsigned long long b) {
    asm("fma.rn.f32x2 %0, %1, %2, %0;" : "+l"(d) : "l"(a), "l"(b));
}
__device__ __forceinline__ float2 upk2(unsigned long long v) {
    float2 r;
    asm("mov.b64 {%0, %1}, %2;" : "=f"(r.x), "=f"(r.y) : "l"(v));
    return r;
}

__device__ __forceinline__ float2 cmulf2(float2 a, float2 w) {
    return make_float2(a.x * w.x - a.y * w.y, a.x * w.y + a.y * w.x);
}

// ---------------------------------------------------------------------------
// Register-resident 128-pt complex FFT across one warp.
// v[t] holds element j = t*32 + lane. Caller loads v BIT-REVERSED; output natural.
// ---------------------------------------------------------------------------
__device__ __forceinline__ void reg_fft128(float2 v[4], int lane) {
#pragma unroll
    for (int s = 0; s < 5; s++) {
        const int mask = 1 << s;
        const bool hi = (lane & mask) != 0;
        const int pos = lane & (mask - 1);
        const float2 w = g_tw[pos << (6 - s)];
#pragma unroll
        for (int t = 0; t < 4; t++) {
            float2 p;
            p.x = __shfl_xor_sync(0xffffffffu, v[t].x, mask);
            p.y = __shfl_xor_sync(0xffffffffu, v[t].y, mask);
            float2 a = hi ? p : v[t];
            float2 b = hi ? v[t] : p;
            float2 bt = cmulf2(b, w);
            v[t] = hi ? make_float2(a.x - bt.x, a.y - bt.y)
                      : make_float2(a.x + bt.x, a.y + bt.y);
        }
    }
    {
        float2 w = g_tw[lane << 1];
        float2 b1 = cmulf2(v[1], w);
        float2 a0 = v[0];
        v[0] = make_float2(a0.x + b1.x, a0.y + b1.y);
        v[1] = make_float2(a0.x - b1.x, a0.y - b1.y);
        float2 b3 = cmulf2(v[3], w);
        float2 a2 = v[2];
        v[2] = make_float2(a2.x + b3.x, a2.y + b3.y);
        v[3] = make_float2(a2.x - b3.x, a2.y - b3.y);
    }
    {
        float2 w0 = g_tw[lane];
        float2 w1 = g_tw[lane + 32];
        float2 b2 = cmulf2(v[2], w0);
        float2 a0 = v[0];
        v[0] = make_float2(a0.x + b2.x, a0.y + b2.y);
        v[2] = make_float2(a0.x - b2.x, a0.y - b2.y);
        float2 b3 = cmulf2(v[3], w1);
        float2 a1 = v[1];
        v[1] = make_float2(a1.x + b3.x, a1.y + b3.y);
        v[3] = make_float2(a1.x - b3.x, a1.y - b3.y);
    }
}

// smem-based padded FFT (what_kernel only)
__device__ __forceinline__ void warp_fft128p(float2* ln, int lane) {
    __syncwarp();
    float2 a0 = ln[FIDX(lane)],      a1 = ln[FIDX(lane + 32)];
    float2 a2 = ln[FIDX(lane + 64)], a3 = ln[FIDX(lane + 96)];
    __syncwarp();
    ln[FIDX(__brev((unsigned)lane) >> 25)]        = a0;
    ln[FIDX(__brev((unsigned)(lane + 32)) >> 25)] = a1;
    ln[FIDX(__brev((unsigned)(lane + 64)) >> 25)] = a2;
    ln[FIDX(__brev((unsigned)(lane + 96)) >> 25)] = a3;
    __syncwarp();
#pragma unroll
    for (int s = 0; s < 7; s++) {
        int half = 1 << s;
#pragma unroll
        for (int t = 0; t < 2; t++) {
            int bf  = lane + t * 32;
            int grp = bf >> s;
            int pos = bf & (half - 1);
            int i0  = (grp << (s + 1)) + pos;
            int i1  = i0 + half;
            float2 w = g_tw[pos << (6 - s)];
            float2 a = ln[FIDX(i0)], b = ln[FIDX(i1)];
            float2 bt = cmulf2(b, w);
            ln[FIDX(i0)] = make_float2(a.x + bt.x, a.y + bt.y);
            ln[FIDX(i1)] = make_float2(a.x - bt.x, a.y - bt.y);
        }
        __syncwarp();
    }
}

__global__ void twiddle_kernel() {
    int j = threadIdx.x;
    if (j < 64) {
        double ang = -2.0 * 3.14159265358979323846 * (double)j / 128.0;
        g_tw[j] = make_float2((float)cos(ang), (float)sin(ang));
    }
}

// ---------------------------------------------------------------------------
// K1: fold BN into projection weights
// ---------------------------------------------------------------------------
__global__ void fold_kernel(const float* __restrict__ w_q, const float* __restrict__ w_k,
                            const float* __restrict__ w_v,
                            const float* __restrict__ gq, const float* __restrict__ bq,
                            const float* __restrict__ mq, const float* __restrict__ vq,
                            const float* __restrict__ gv, const float* __restrict__ bv,
                            const float* __restrict__ mv, const float* __restrict__ vvar) {
    int o = blockIdx.x * blockDim.x + threadIdx.x;
    if (o >= 384) return;
    if (o < 64) {
        float inv = gq[o] * rsqrtf(vq[o] + EPS_);
        g_bias[o] = bq[o] - mq[o] * inv;
        for (int c = 0; c < 256; c++) g_wfold[o * 256 + c] = w_q[o * 256 + c] * inv;
    } else if (o < 128) {
        int i = o - 64;
        g_bias[o] = 0.f;
        for (int c = 0; c < 256; c++) g_wfold[o * 256 + c] = w_k[i * 256 + c];
    } else {
        int i = o - 128;
        float inv = gv[i] * rsqrtf(vvar[i] + EPS_);
        g_bias[o] = bv[i] - mv[i] * inv;
        for (int c = 0; c < 256; c++) g_wfold[o * 256 + c] = w_v[i * 256 + c] * inv;
    }
}

// ---------------------------------------------------------------------------
// K2: projection GEMM
// ---------------------------------------------------------------------------
__global__ __launch_bounds__(256) void proj_gemm_kernel(const float* __restrict__ x) {
    __shared__ float As[16][64];
    __shared__ float Bs[16][128];
    const int b  = blockIdx.z;
    const int m0 = blockIdx.y * 64;
    const int n0 = blockIdx.x * 128;
    const int tid = threadIdx.x;
    const int tx = tid & 15, ty = tid >> 4;
    const float* xb = x + (size_t)b * C_ * N_ + n0;

    unsigned long long acc[4][4];
#pragma unroll
    for (int j = 0; j < 4; j++)
#pragma unroll
        for (int i = 0; i < 4; i++) acc[j][i] = 0ull;

    for (int k0 = 0; k0 < 256; k0 += 16) {
#pragma unroll
        for (int l = 0; l < 4; l++) {
            int e = tid + l * 256;
            int m = e & 63, kk = e >> 6;
            As[kk][m] = g_wfold[(m0 + m) * 256 + k0 + kk];
        }
#pragma unroll
        for (int l = 0; l < 8; l++) {
            int e = tid + l * 256;
            int kk = e >> 7, n = e & 127;
            Bs[kk][n] = xb[(size_t)(k0 + kk) * N_ + n];
        }
        __syncthreads();
#pragma unroll
        for (int kk = 0; kk < 16; kk++) {
            float4 a4 = *(const float4*)&As[kk][ty * 4];
            float4 b0 = *(const float4*)&Bs[kk][tx * 8];
            float4 b1 = *(const float4*)&Bs[kk][tx * 8 + 4];
            unsigned long long bp[4] = {pk2(b0.x, b0.y), pk2(b0.z, b0.w),
                                        pk2(b1.x, b1.y), pk2(b1.z, b1.w)};
            float av[4] = {a4.x, a4.y, a4.z, a4.w};
#pragma unroll
            for (int j = 0; j < 4; j++) {
                unsigned long long ap = pk2(av[j], av[j]);
#pragma unroll
                for (int i = 0; i < 4; i++) ffma2(acc[j][i], ap, bp[i]);
            }
        }
        __syncthreads();
    }
#pragma unroll
    for (int j = 0; j < 4; j++) {
        int m = m0 + ty * 4 + j;
        float bi = g_bias[m];
        float* dst = g_proj + ((size_t)b * 384 + m) * N_ + n0 + tx * 8;
#pragma unroll
        for (int i = 0; i < 4; i++) {
            float2 v = upk2(acc[j][i]);
            dst[i * 2]     = v.x + bi;
            dst[i * 2 + 1] = v.y + bi;
        }
    }
}

// ---------------------------------------------------------------------------
// F1: forward FFT of v rows — two real rows per FFT, register-resident FFT.
// ---------------------------------------------------------------------------
__global__ __launch_bounds__(256) void rhat_kernel() {
    __shared__ float2 lines[8][128];
    const int wid = threadIdx.x >> 5, lane = threadIdx.x & 31;
    const int p  = blockIdx.x * 8 + wid;    // pair id
    const int yp = p & 31;                  // rows 2yp, 2yp+1
    const int u  = (p >> 5) & 3;
    const int dv = (p >> 7) & 63;
    const int b  = p >> 13;
    const float* src = g_proj + ((size_t)(b * 384 + 128 + u * 64 + dv)) * N_ + (yp * 2) * 64;
    float2* ln = lines[wid];
    ln[lane]      = make_float2(src[lane],      src[64 + lane]);
    ln[lane + 32] = make_float2(src[lane + 32], src[96 + lane]);
    __syncwarp();
    float2 v[4];
#pragma unroll
    for (int t = 0; t < 4; t++) {
        int j = t * 32 + lane;
        int r = __brev((unsigned)j) >> 25;
        v[t] = (r < 64) ? ln[r] : make_float2(0.f, 0.f);
    }
    reg_fft128(v, lane);
    __syncwarp();
#pragma unroll
    for (int t = 0; t < 4; t++) ln[t * 32 + lane] = v[t];
    __syncwarp();
    float2* d0 = g_Rhat + ((size_t)(((b * 64 + dv) * 4 + u) * 64 + yp * 2)) * 65;
    float2* d1 = d0 + 65;
#pragma unroll
    for (int t = 0; t < 2; t++) {
        int f = lane + t * 32;
        int n = (128 - f) & 127;
        float2 zf = ln[f], zn = ln[n];
        d0[f] = make_float2(0.5f * (zf.x + zn.x), 0.5f * (zf.y - zn.y));
        d1[f] = make_float2(0.5f * (zf.y + zn.y), 0.5f * (zn.x - zf.x));
    }
    if (lane == 0) {
        float2 z = ln[64];
        d0[64] = make_float2(z.x, 0.f);
        d1[64] = make_float2(z.y, 0.f);
    }
}

// ---------------------------------------------------------------------------
// K3: softmax over positions for k rows
// ---------------------------------------------------------------------------
__global__ __launch_bounds__(256) void softmax_kernel() {
    __shared__ float red[8];
    const int row = blockIdx.x;
    const int b = row >> 6, r = row & 63;
    float* p = g_proj + ((size_t)b * 384 + 64 + r) * N_;
    const int tid = threadIdx.x, lane = tid & 31, wid = tid >> 5;

    float v[16];
    float mx = -3.4e38f;
#pragma unroll
    for (int l = 0; l < 16; l++) {
        v[l] = p[tid + l * 256];
        mx = fmaxf(mx, v[l]);
    }
#pragma unroll
    for (int o = 16; o; o >>= 1) mx = fmaxf(mx, __shfl_xor_sync(0xffffffffu, mx, o));
    if (!lane) red[wid] = mx;
    __syncthreads();
    mx = red[0];
#pragma unroll
    for (int w = 1; w < 8; w++) mx = fmaxf(mx, red[w]);

    float s = 0.f;
#pragma unroll
    for (int l = 0; l < 16; l++) {
        v[l] = expf(v[l] - mx);
        s += v[l];
    }
#pragma unroll
    for (int o = 16; o; o >>= 1) s += __shfl_xor_sync(0xffffffffu, s, o);
    __syncthreads();
    if (!lane) red[wid] = s;
    __syncthreads();
    s = 0.f;
#pragma unroll
    for (int w = 0; w < 8; w++) s += red[w];
    float inv = 1.0f / s;
#pragma unroll
    for (int l = 0; l < 16; l++) p[tid + l * 256] = v[l] * inv;
}

// ---------------------------------------------------------------------------
// K4: Lc partials + reduce
// ---------------------------------------------------------------------------
__global__ __launch_bounds__(256) void lc_partial_kernel() {
    __shared__ float ks[16][64];
    __shared__ float vsm[64][65];
    const int s = blockIdx.x, u = blockIdx.y, b = blockIdx.z;
    const int tid = threadIdx.x;
    const int kk = tid >> 4, vg = tid & 15;
    float acc[4] = {0.f, 0.f, 0.f, 0.f};
    const float* kbase = g_proj + ((size_t)b * 384 + 64 + u * 16) * N_;
    const float* vbase = g_proj + ((size_t)b * 384 + 128 + u * 64) * N_;
    const int m0b = s * 512;

    for (int mc = 0; mc < 512; mc += 64) {
        const int m0 = m0b + mc;
#pragma unroll
        for (int l = 0; l < 4; l++) {
            int e = tid + l * 256;
            ks[e >> 6][e & 63] = kbase[(size_t)(e >> 6) * N_ + m0 + (e & 63)];
        }
#pragma unroll
        for (int l = 0; l < 16; l++) {
            int e = tid + l * 256;
            vsm[e >> 6][e & 63] = vbase[(size_t)(e >> 6) * N_ + m0 + (e & 63)];
        }
        __syncthreads();
#pragma unroll 8
        for (int m = 0; m < 64; m++) {
            float kv = ks[kk][m];
#pragma unroll
            for (int j = 0; j < 4; j++) acc[j] = fmaf(kv, vsm[vg * 4 + j][m], acc[j]);
        }
        __syncthreads();
    }
    float* dst = g_LcPart + (((size_t)b * 4 + u) * 8 + s) * 1024 + kk * 64 + vg * 4;
#pragma unroll
    for (int j = 0; j < 4; j++) dst[j] = acc[j];
}

__global__ void lc_reduce_kernel() {
    const int b = blockIdx.x;
    const int t = threadIdx.x;  // 1024
    float s = 0.f;
#pragma unroll
    for (int p = 0; p < 32; p++) s += g_LcPart[((size_t)b * 32 + p) * 1024 + t];
    g_Lc[b * 1024 + t] = s;
}

// ---------------------------------------------------------------------------
// F0: FFT of position kernel rows -> g_What2 (float2, padded to 1473 rows)
// ---------------------------------------------------------------------------
__global__ __launch_bounds__(256) void what_kernel(const float* __restrict__ w_pos) {
    __shared__ float2 lines[8][FLINE];
    const int wid = threadIdx.x >> 5, lane = threadIdx.x & 31;
    const int row = blockIdx.x * 8 + wid;
    if (row >= 1472) return;
    const int k = row / 92;
    const int rem = row - k * 92;
    const int u = rem / 23;
    const int dy = rem - u * 23;
    float2* ln = lines[wid];
#pragma unroll
    for (int t = 0; t < 4; t++) ln[FIDX(lane + t * 32)] = make_float2(0.f, 0.f);
    __syncwarp();
    if (lane < 23) {
        float w = w_pos[(size_t)(k * 4 + u) * 529 + dy * 23 + lane];
        ln[FIDX((11 - lane) & 127)] = make_float2(w, 0.f);
    }
    warp_fft128p(ln, lane);
    g_What2[(size_t)row * WSTRIDE + lane]      = ln[FIDX(lane)];
    g_What2[(size_t)row * WSTRIDE + lane + 32] = ln[FIDX(lane + 32)];
    if (lane == 0) g_What2[(size_t)row * WSTRIDE + 64] = ln[FIDX(64)];
}

// ---------------------------------------------------------------------------
// MEGA fused v7: 256 threads, 2 CTAs/SM. FFMA2-packed mix with 1-deep W
// prefetch + register inverse FFT + fused combine.
// smem: Gs 4160 f2 + Rs 7800 f2 = 95,680 B -> 2 CTAs/SM
// ---------------------------------------------------------------------------
__global__ __launch_bounds__(256, 2) void mega_kernel(const float* __restrict__ b_pos,
                                                      float* __restrict__ out) {
    extern __shared__ float2 sm[];
    float2* Gs = sm;                        // 4160 float2 (4y x 16k x 65f)
    float2* Rs = sm + 4160;                 // 7800 float2 (halo 4u x 30 x 65)
    const int dv = blockIdx.x, b = blockIdx.y;
    const int tid  = threadIdx.x;
    const int lane = tid & 31;
    const int wrp  = tid >> 5;              // 0..7
    const int kq = wrp & 3;
    const int fc = wrp >> 2;
    const int f  = fc * 32 + lane;          // 0..63
    const int bdv = b * 64 + dv;
    const int c_y = tid >> 4, c_k = tid & 15;
    const int k0 = wrp * 2, k1 = k0 + 1;
    const float add0 = b_pos[k0] + g_Lc[b * 1024 + k0 * 64 + dv];
    const float add1 = b_pos[k1] + g_Lc[b * 1024 + k1 * 64 + dv];
    const float sc = 1.0f / 128.0f;
    float* tile = (float*)Rs;               // alias: Rs[0..4095] f2, [16k][512px]

    for (int yt = 0; yt < 8; yt++) {
        const int y0 = yt * 8;
        __syncthreads();
        // ---- stage Rs halo rows y0-11 .. y0+18 (30 rows x 4u x 65f) ----
        for (int i = tid; i < 7800; i += 256) {
            int u   = i / 1950;
            int rem = i - u * 1950;
            int rr  = rem / 65;
            int ff  = rem - rr * 65;
            int y   = y0 + rr - 11;
            float2 val = make_float2(0.f, 0.f);
            if (y >= 0 && y < 64)
                val = g_Rhat[(((size_t)bdv * 4 + u) * 64 + y) * 65 + ff];
            Rs[i] = val;
        }
        __syncthreads();

        // ---- mix: FFMA2-packed schoolbook, flattened loop, 1-deep W prefetch ----
        // acc2[i][j] = (re, im) packed. re += r.x*w.x - r.y*w.y ; im += r.x*w.y + r.y*w.x
        // -> acc2 += (r.x,r.x)*(w.x,w.y) ; acc2 += (r.y,r.y)*(-w.y,w.x)
        unsigned long long acc2[8][4];
#pragma unroll
        for (int i = 0; i < 8; i++)
#pragma unroll
            for (int j = 0; j < 4; j++) acc2[i][j] = 0ull;

        {
            const float2* w0p = g_What2 + (size_t)((kq * 4 + 0) * 92) * WSTRIDE + f;
            const float2* w1p = g_What2 + (size_t)((kq * 4 + 1) * 92) * WSTRIDE + f;
            const float2* w2p = g_What2 + (size_t)((kq * 4 + 2) * 92) * WSTRIDE + f;
            const float2* w3p = g_What2 + (size_t)((kq * 4 + 3) * 92) * WSTRIDE + f;
            const float2* rp  = Rs + f;     // row cursor: (u*30 + dy)*65
            int dy = 0;
            // packed current W: A=(w.x,w.y), B=(-w.y,w.x)
            unsigned long long wA[4], wB[4];
            {
                float2 t0 = w0p[0], t1 = w1p[0], t2 = w2p[0], t3 = w3p[0];
                wA[0] = pk2(t0.x, t0.y); wB[0] = pk2(-t0.y, t0.x);
                wA[1] = pk2(t1.x, t1.y); wB[1] = pk2(-t1.y, t1.x);
                wA[2] = pk2(t2.x, t2.y); wB[2] = pk2(-t2.y, t2.x);
                wA[3] = pk2(t3.x, t3.y); wB[3] = pk2(-t3.y, t3.x);
            }
#pragma unroll 1
            for (int it = 0; it < 92; it++) {
                // prefetch next iteration's W (padded table: it+1 <= 92 in-bounds)
                const int ni = (it + 1) * WSTRIDE;
                float2 nw0 = w0p[ni], nw1 = w1p[ni], nw2 = w2p[ni], nw3 = w3p[ni];
#pragma unroll
                for (int i = 0; i < 8; i++) {
                    float2 r = rp[i * 65];
                    unsigned long long rx2 = pk2(r.x, r.x);
                    unsigned long long ry2 = pk2(r.y, r.y);
                    ffma2(acc2[i][0], rx2, wA[0]); ffma2(acc2[i][0], ry2, wB[0]);
                    ffma2(acc2[i][1], rx2, wA[1]); ffma2(acc2[i][1], ry2, wB[1]);
                    ffma2(acc2[i][2], rx2, wA[2]); ffma2(acc2[i][2], ry2, wB[2]);
                    ffma2(acc2[i][3], rx2, wA[3]); ffma2(acc2[i][3], ry2, wB[3]);
                }
                wA[0] = pk2(nw0.x, nw0.y); wB[0] = pk2(-nw0.y, nw0.x);
                wA[1] = pk2(nw1.x, nw1.y); wB[1] = pk2(-nw1.y, nw1.x);
                wA[2] = pk2(nw2.x, nw2.y); wB[2] = pk2(-nw2.y, nw2.x);
                wA[3] = pk2(nw3.x, nw3.y); wB[3] = pk2(-nw3.y, nw3.x);
                rp += 65;
                if (++dy == 23) { dy = 0; rp += 7 * 65; }   // skip to next u block
            }
        }

        // ---- f = 64 Nyquist bin (threads 0..127), result kept in regs ----
        float2 ny = make_float2(0.f, 0.f);
        if (tid < 128) {
#pragma unroll 1
            for (int u = 0; u < 4; u++) {
                const float2* rptr = Rs + (u * 30 + c_y) * 65 + 64;
                const float2* wp = g_What2 + ((size_t)(c_k * 92 + u * 23)) * WSTRIDE + 64;
#pragma unroll
                for (int dy = 0; dy < 23; dy++) {
                    float2 r = rptr[dy * 65];
                    float2 w = wp[dy * WSTRIDE];
                    ny.x = fmaf(r.x, w.x, ny.x); ny.x = fmaf(-r.y, w.y, ny.x);
                    ny.y = fmaf(r.x, w.y, ny.y); ny.y = fmaf(r.y, w.x, ny.y);
                }
            }
        }

        // ---- two G halves: write 4 y rows -> register inverse FFT -> tile ----
#pragma unroll 1
        for (int half = 0; half < 2; half++) {
            __syncthreads();   // Gs free; Rs clobber OK (mix/ny done; tile alias)
#pragma unroll
            for (int i = 0; i < 4; i++)
#pragma unroll
                for (int j = 0; j < 4; j++)
                    Gs[(i * 16 + kq * 4 + j) * 65 + f] = upk2(acc2[half * 4 + i][j]);
            if (tid < 128 && (c_y >> 2) == half)
                Gs[((c_y & 3) * 16 + c_k) * 65 + 64] = ny;
            __syncthreads();   // Gs half complete

            // inverse: warp = k-pair, 4 lines, fully in registers
#pragma unroll 1
            for (int l = 0; l < 4; l++) {
                const float2* G0 = Gs + (l * 16 + k0) * 65;
                const float2* G1 = Gs + (l * 16 + k1) * 65;
                float2 v[4];
#pragma unroll
                for (int t = 0; t < 4; t++) {
                    int j = t * 32 + lane;
                    int ff = __brev((unsigned)j) >> 25;   // bit-reversed gather
                    float2 z;
                    if (ff <= 64) {
                        float2 a = G0[ff], c = G1[ff];
                        z = make_float2(a.x - c.y, a.y + c.x);
                    } else {
                        int g = 128 - ff;
                        float2 a = G0[g], c = G1[g];
                        z = make_float2(a.x + c.y, -a.y + c.x);
                    }
                    v[t] = make_float2(z.x, -z.y);        // conj for inverse
                }
                reg_fft128(v, lane);
                const int yl = half * 4 + l;
#pragma unroll
                for (int t = 0; t < 2; t++) {
                    int x = t * 32 + lane;
                    float2 o = v[t];
                    tile[k0 * 512 + yl * 64 + x] = o.x * sc + add0;
                    tile[k1 * 512 + yl * 64 + x] = -o.y * sc + add1;
                }
            }
        }
        __syncthreads();   // tile complete (both halves)

        // ---- combine: thread = px (two passes), 4 heads each ----
#pragma unroll
        for (int pp = 0; pp < 2; pp++) {
            const int px = tid + pp * 256;
            const int n = y0 * 64 + px;
            const float* qb = g_proj + (size_t)b * 384 * N_ + n;
#pragma unroll
            for (int h = 0; h < 4; h++) {
                float a = 0.f;
#pragma unroll
                for (int k = 0; k < 16; k++)
                    a = fmaf(qb[(size_t)(h * 16 + k) * N_], tile[k * 512 + px], a);
                out[((size_t)b * 256 + h * 64 + dv) * N_ + n] = a;
            }
        }
    }
}

// ---------------------------------------------------------------------------
extern "C" void kernel_launch(void* const* d_in, const int* in_sizes, int n_in,
                              void* d_out, int out_size) {
    const float* x     = (const float*)d_in[0];
    const float* w_q   = (const float*)d_in[1];
    const float* w_k   = (const float*)d_in[2];
    const float* w_v   = (const float*)d_in[3];
    const float* gq    = (const float*)d_in[4];
    const float* bq    = (const float*)d_in[5];
    const float* mq    = (const float*)d_in[6];
    const float* vq    = (const float*)d_in[7];
    const float* gv    = (const float*)d_in[8];
    const float* bv    = (const float*)d_in[9];
    const float* mv    = (const float*)d_in[10];
    const float* vvar  = (const float*)d_in[11];
    const float* w_pos = (const float*)d_in[12];
    const float* b_pos = (const float*)d_in[13];
    float* out = (float*)d_out;

    const int MEGA_SMEM = (4160 + 7800) * sizeof(float2);   // 95,680 B -> 2 CTAs/SM
    cudaFuncSetAttribute(mega_kernel, cudaFuncAttributeMaxDynamicSharedMemorySize, MEGA_SMEM);

    twiddle_kernel<<<1, 64>>>();
    fold_kernel<<<2, 256>>>(w_q, w_k, w_v, gq, bq, mq, vq, gv, bv, mv, vvar);
    proj_gemm_kernel<<<dim3(32, 6, 16), 256>>>(x);
    rhat_kernel<<<16384, 256>>>();        // 4th launch -> ncu capture slot
    softmax_kernel<<<1024, 256>>>();
    lc_partial_kernel<<<dim3(8, 4, 16), 256>>>();
    lc_reduce_kernel<<<16, 1024>>>();
    what_kernel<<<184, 256>>>(w_pos);
    mega_kernel<<<dim3(64, 16), 256, MEGA_SMEM>>>(b_pos, out);
}

// round 16
// speedup vs baseline: 1.0257x; 1.0257x over previous
#include <cuda_runtime.h>
#include <math.h>

// Problem constants
#define B_   16
#define C_   256
#define HH_  64
#define WW_  64
#define N_   4096      // HH*WW
#define K_   16
#define H_   4
#define U_   4
#define R_   23
#define DV_  64
#define EPS_ 1e-3f

#define WSTRIDE 66     // f-stride of W-hat table (float2 units)
#define FIDX(i) ((i) + ((i) >> 3))   // padded FFT line index (what_kernel only)
#define FLINE 144

// Scratch (device globals; no allocation allowed)
__device__ float  g_wfold[384 * 256];
__device__ float  g_bias[384];
__device__ float  g_proj[(size_t)B_ * 384 * N_];          // rows 0-63 q, 64-127 k, 128-383 v
__device__ float  g_LcPart[(size_t)B_ * 32 * 1024];
__device__ float  g_Lc[B_ * K_ * DV_];                    // [b][k][dv]
__device__ float2 g_tw[64];                               // fwd twiddles W_128^j
__device__ float2 g_What2[1473 * WSTRIDE];                // [row=k*92+u*23+dy][f] (+1 pad row)
__device__ float2 g_Rhat[(size_t)262144 * 65];            // [(b*64+dv)*4+u][y][f]

// ---- packed fp32x2 helpers (proj GEMM only) --------------------------------
__device__ __forceinline__ unsigned long long pk2(float lo, float hi) {
    unsigned long long r;
    asm("mov.b64 %0, {%1, %2};" : "=l"(r) : "f"(lo), "f"(hi));
    return r;
}
__device__ __forceinline__ void ffma2(unsigned long long& d, unsigned long long a,
                                      unsigned long long b) {
    asm("fma.rn.f32x2 %0, %1, %2, %0;" : "+l"(d) : "l"(a), "l"(b));
}
__device__ __forceinline__ float2 upk2(unsigned long long v) {
    float2 r;
    asm("mov.b64 {%0, %1}, %2;" : "=f"(r.x), "=f"(r.y) : "l"(v));
    return r;
}

__device__ __forceinline__ float2 cmulf2(float2 a, float2 w) {
    return make_float2(a.x * w.x - a.y * w.y, a.x * w.y + a.y * w.x);
}

// ---------------------------------------------------------------------------
// Register-resident 128-pt complex FFT across one warp.
// v[t] holds element j = t*32 + lane. Caller loads v BIT-REVERSED; output natural.
// ---------------------------------------------------------------------------
__device__ __forceinline__ void reg_fft128(float2 v[4], int lane) {
#pragma unroll
    for (int s = 0; s < 5; s++) {
        const int mask = 1 << s;
        const bool hi = (lane & mask) != 0;
        const int pos = lane & (mask - 1);
        const float2 w = g_tw[pos << (6 - s)];
#pragma unroll
        for (int t = 0; t < 4; t++) {
            float2 p;
            p.x = __shfl_xor_sync(0xffffffffu, v[t].x, mask);
            p.y = __shfl_xor_sync(0xffffffffu, v[t].y, mask);
            float2 a = hi ? p : v[t];
            float2 b = hi ? v[t] : p;
            float2 bt = cmulf2(b, w);
            v[t] = hi ? make_float2(a.x - bt.x, a.y - bt.y)
                      : make_float2(a.x + bt.x, a.y + bt.y);
        }
    }
    {
        float2 w = g_tw[lane << 1];
        float2 b1 = cmulf2(v[1], w);
        float2 a0 = v[0];
        v[0] = make_float2(a0.x + b1.x, a0.y + b1.y);
        v[1] = make_float2(a0.x - b1.x, a0.y - b1.y);
        float2 b3 = cmulf2(v[3], w);
        float2 a2 = v[2];
        v[2] = make_float2(a2.x + b3.x, a2.y + b3.y);
        v[3] = make_float2(a2.x - b3.x, a2.y - b3.y);
    }
    {
        float2 w0 = g_tw[lane];
        float2 w1 = g_tw[lane + 32];
        float2 b2 = cmulf2(v[2], w0);
        float2 a0 = v[0];
        v[0] = make_float2(a0.x + b2.x, a0.y + b2.y);
        v[2] = make_float2(a0.x - b2.x, a0.y - b2.y);
        float2 b3 = cmulf2(v[3], w1);
        float2 a1 = v[1];
        v[1] = make_float2(a1.x + b3.x, a1.y + b3.y);
        v[3] = make_float2(a1.x - b3.x, a1.y - b3.y);
    }
}

// smem-based padded FFT (what_kernel only)
__device__ __forceinline__ void warp_fft128p(float2* ln, int lane) {
    __syncwarp();
    float2 a0 = ln[FIDX(lane)],      a1 = ln[FIDX(lane + 32)];
    float2 a2 = ln[FIDX(lane + 64)], a3 = ln[FIDX(lane + 96)];
    __syncwarp();
    ln[FIDX(__brev((unsigned)lane) >> 25)]        = a0;
    ln[FIDX(__brev((unsigned)(lane + 32)) >> 25)] = a1;
    ln[FIDX(__brev((unsigned)(lane + 64)) >> 25)] = a2;
    ln[FIDX(__brev((unsigned)(lane + 96)) >> 25)] = a3;
    __syncwarp();
#pragma unroll
    for (int s = 0; s < 7; s++) {
        int half = 1 << s;
#pragma unroll
        for (int t = 0; t < 2; t++) {
            int bf  = lane + t * 32;
            int grp = bf >> s;
            int pos = bf & (half - 1);
            int i0  = (grp << (s + 1)) + pos;
            int i1  = i0 + half;
            float2 w = g_tw[pos << (6 - s)];
            float2 a = ln[FIDX(i0)], b = ln[FIDX(i1)];
            float2 bt = cmulf2(b, w);
            ln[FIDX(i0)] = make_float2(a.x + bt.x, a.y + bt.y);
            ln[FIDX(i1)] = make_float2(a.x - bt.x, a.y - bt.y);
        }
        __syncwarp();
    }
}

__global__ void twiddle_kernel() {
    int j = threadIdx.x;
    if (j < 64) {
        double ang = -2.0 * 3.14159265358979323846 * (double)j / 128.0;
        g_tw[j] = make_float2((float)cos(ang), (float)sin(ang));
    }
}

// ---------------------------------------------------------------------------
// K1: fold BN into projection weights
// ---------------------------------------------------------------------------
__global__ void fold_kernel(const float* __restrict__ w_q, const float* __restrict__ w_k,
                            const float* __restrict__ w_v,
                            const float* __restrict__ gq, const float* __restrict__ bq,
                            const float* __restrict__ mq, const float* __restrict__ vq,
                            const float* __restrict__ gv, const float* __restrict__ bv,
                            const float* __restrict__ mv, const float* __restrict__ vvar) {
    int o = blockIdx.x * blockDim.x + threadIdx.x;
    if (o >= 384) return;
    if (o < 64) {
        float inv = gq[o] * rsqrtf(vq[o] + EPS_);
        g_bias[o] = bq[o] - mq[o] * inv;
        for (int c = 0; c < 256; c++) g_wfold[o * 256 + c] = w_q[o * 256 + c] * inv;
    } else if (o < 128) {
        int i = o - 64;
        g_bias[o] = 0.f;
        for (int c = 0; c < 256; c++) g_wfold[o * 256 + c] = w_k[i * 256 + c];
    } else {
        int i = o - 128;
        float inv = gv[i] * rsqrtf(vvar[i] + EPS_);
        g_bias[o] = bv[i] - mv[i] * inv;
        for (int c = 0; c < 256; c++) g_wfold[o * 256 + c] = w_v[i * 256 + c] * inv;
    }
}

// ---------------------------------------------------------------------------
// K2: projection GEMM
// ---------------------------------------------------------------------------
__global__ __launch_bounds__(256) void proj_gemm_kernel(const float* __restrict__ x) {
    __shared__ float As[16][64];
    __shared__ float Bs[16][128];
    const int b  = blockIdx.z;
    const int m0 = blockIdx.y * 64;
    const int n0 = blockIdx.x * 128;
    const int tid = threadIdx.x;
    const int tx = tid & 15, ty = tid >> 4;
    const float* xb = x + (size_t)b * C_ * N_ + n0;

    unsigned long long acc[4][4];
#pragma unroll
    for (int j = 0; j < 4; j++)
#pragma unroll
        for (int i = 0; i < 4; i++) acc[j][i] = 0ull;

    for (int k0 = 0; k0 < 256; k0 += 16) {
#pragma unroll
        for (int l = 0; l < 4; l++) {
            int e = tid + l * 256;
            int m = e & 63, kk = e >> 6;
            As[kk][m] = g_wfold[(m0 + m) * 256 + k0 + kk];
        }
#pragma unroll
        for (int l = 0; l < 8; l++) {
            int e = tid + l * 256;
            int kk = e >> 7, n = e & 127;
            Bs[kk][n] = xb[(size_t)(k0 + kk) * N_ + n];
        }
        __syncthreads();
#pragma unroll
        for (int kk = 0; kk < 16; kk++) {
            float4 a4 = *(const float4*)&As[kk][ty * 4];
            float4 b0 = *(const float4*)&Bs[kk][tx * 8];
            float4 b1 = *(const float4*)&Bs[kk][tx * 8 + 4];
            unsigned long long bp[4] = {pk2(b0.x, b0.y), pk2(b0.z, b0.w),
                                        pk2(b1.x, b1.y), pk2(b1.z, b1.w)};
            float av[4] = {a4.x, a4.y, a4.z, a4.w};
#pragma unroll
            for (int j = 0; j < 4; j++) {
                unsigned long long ap = pk2(av[j], av[j]);
#pragma unroll
                for (int i = 0; i < 4; i++) ffma2(acc[j][i], ap, bp[i]);
            }
        }
        __syncthreads();
    }
#pragma unroll
    for (int j = 0; j < 4; j++) {
        int m = m0 + ty * 4 + j;
        float bi = g_bias[m];
        float* dst = g_proj + ((size_t)b * 384 + m) * N_ + n0 + tx * 8;
#pragma unroll
        for (int i = 0; i < 4; i++) {
            float2 v = upk2(acc[j][i]);
            dst[i * 2]     = v.x + bi;
            dst[i * 2 + 1] = v.y + bi;
        }
    }
}

// ---------------------------------------------------------------------------
// F1: forward FFT of v rows — two real rows per FFT, register-resident FFT.
// ---------------------------------------------------------------------------
__global__ __launch_bounds__(256) void rhat_kernel() {
    __shared__ float2 lines[8][128];
    const int wid = threadIdx.x >> 5, lane = threadIdx.x & 31;
    const int p  = blockIdx.x * 8 + wid;    // pair id
    const int yp = p & 31;                  // rows 2yp, 2yp+1
    const int u  = (p >> 5) & 3;
    const int dv = (p >> 7) & 63;
    const int b  = p >> 13;
    const float* src = g_proj + ((size_t)(b * 384 + 128 + u * 64 + dv)) * N_ + (yp * 2) * 64;
    float2* ln = lines[wid];
    ln[lane]      = make_float2(src[lane],      src[64 + lane]);
    ln[lane + 32] = make_float2(src[lane + 32], src[96 + lane]);
    __syncwarp();
    float2 v[4];
#pragma unroll
    for (int t = 0; t < 4; t++) {
        int j = t * 32 + lane;
        int r = __brev((unsigned)j) >> 25;
        v[t] = (r < 64) ? ln[r] : make_float2(0.f, 0.f);
    }
    reg_fft128(v, lane);
    __syncwarp();
#pragma unroll
    for (int t = 0; t < 4; t++) ln[t * 32 + lane] = v[t];
    __syncwarp();
    float2* d0 = g_Rhat + ((size_t)(((b * 64 + dv) * 4 + u) * 64 + yp * 2)) * 65;
    float2* d1 = d0 + 65;
#pragma unroll
    for (int t = 0; t < 2; t++) {
        int f = lane + t * 32;
        int n = (128 - f) & 127;
        float2 zf = ln[f], zn = ln[n];
        d0[f] = make_float2(0.5f * (zf.x + zn.x), 0.5f * (zf.y - zn.y));
        d1[f] = make_float2(0.5f * (zf.y + zn.y), 0.5f * (zn.x - zf.x));
    }
    if (lane == 0) {
        float2 z = ln[64];
        d0[64] = make_float2(z.x, 0.f);
        d1[64] = make_float2(z.y, 0.f);
    }
}

// ---------------------------------------------------------------------------
// K3: softmax over positions for k rows
// ---------------------------------------------------------------------------
__global__ __launch_bounds__(256) void softmax_kernel() {
    __shared__ float red[8];
    const int row = blockIdx.x;
    const int b = row >> 6, r = row & 63;
    float* p = g_proj + ((size_t)b * 384 + 64 + r) * N_;
    const int tid = threadIdx.x, lane = tid & 31, wid = tid >> 5;

    float v[16];
    float mx = -3.4e38f;
#pragma unroll
    for (int l = 0; l < 16; l++) {
        v[l] = p[tid + l * 256];
        mx = fmaxf(mx, v[l]);
    }
#pragma unroll
    for (int o = 16; o; o >>= 1) mx = fmaxf(mx, __shfl_xor_sync(0xffffffffu, mx, o));
    if (!lane) red[wid] = mx;
    __syncthreads();
    mx = red[0];
#pragma unroll
    for (int w = 1; w < 8; w++) mx = fmaxf(mx, red[w]);

    float s = 0.f;
#pragma unroll
    for (int l = 0; l < 16; l++) {
        v[l] = expf(v[l] - mx);
        s += v[l];
    }
#pragma unroll
    for (int o = 16; o; o >>= 1) s += __shfl_xor_sync(0xffffffffu, s, o);
    __syncthreads();
    if (!lane) red[wid] = s;
    __syncthreads();
    s = 0.f;
#pragma unroll
    for (int w = 0; w < 8; w++) s += red[w];
    float inv = 1.0f / s;
#pragma unroll
    for (int l = 0; l < 16; l++) p[tid + l * 256] = v[l] * inv;
}

// ---------------------------------------------------------------------------
// K4: Lc partials + reduce
// ---------------------------------------------------------------------------
__global__ __launch_bounds__(256) void lc_partial_kernel() {
    __shared__ float ks[16][64];
    __shared__ float vsm[64][65];
    const int s = blockIdx.x, u = blockIdx.y, b = blockIdx.z;
    const int tid = threadIdx.x;
    const int kk = tid >> 4, vg = tid & 15;
    float acc[4] = {0.f, 0.f, 0.f, 0.f};
    const float* kbase = g_proj + ((size_t)b * 384 + 64 + u * 16) * N_;
    const float* vbase = g_proj + ((size_t)b * 384 + 128 + u * 64) * N_;
    const int m0b = s * 512;

    for (int mc = 0; mc < 512; mc += 64) {
        const int m0 = m0b + mc;
#pragma unroll
        for (int l = 0; l < 4; l++) {
            int e = tid + l * 256;
            ks[e >> 6][e & 63] = kbase[(size_t)(e >> 6) * N_ + m0 + (e & 63)];
        }
#pragma unroll
        for (int l = 0; l < 16; l++) {
            int e = tid + l * 256;
            vsm[e >> 6][e & 63] = vbase[(size_t)(e >> 6) * N_ + m0 + (e & 63)];
        }
        __syncthreads();
#pragma unroll 8
        for (int m = 0; m < 64; m++) {
            float kv = ks[kk][m];
#pragma unroll
            for (int j = 0; j < 4; j++) acc[j] = fmaf(kv, vsm[vg * 4 + j][m], acc[j]);
        }
        __syncthreads();
    }
    float* dst = g_LcPart + (((size_t)b * 4 + u) * 8 + s) * 1024 + kk * 64 + vg * 4;
#pragma unroll
    for (int j = 0; j < 4; j++) dst[j] = acc[j];
}

__global__ void lc_reduce_kernel() {
    const int b = blockIdx.x;
    const int t = threadIdx.x;  // 1024
    float s = 0.f;
#pragma unroll
    for (int p = 0; p < 32; p++) s += g_LcPart[((size_t)b * 32 + p) * 1024 + t];
    g_Lc[b * 1024 + t] = s;
}

// ---------------------------------------------------------------------------
// F0: FFT of position kernel rows -> g_What2 (float2, padded to 1473 rows)
// ---------------------------------------------------------------------------
__global__ __launch_bounds__(256) void what_kernel(const float* __restrict__ w_pos) {
    __shared__ float2 lines[8][FLINE];
    const int wid = threadIdx.x >> 5, lane = threadIdx.x & 31;
    const int row = blockIdx.x * 8 + wid;
    if (row >= 1472) return;
    const int k = row / 92;
    const int rem = row - k * 92;
    const int u = rem / 23;
    const int dy = rem - u * 23;
    float2* ln = lines[wid];
#pragma unroll
    for (int t = 0; t < 4; t++) ln[FIDX(lane + t * 32)] = make_float2(0.f, 0.f);
    __syncwarp();
    if (lane < 23) {
        float w = w_pos[(size_t)(k * 4 + u) * 529 + dy * 23 + lane];
        ln[FIDX((11 - lane) & 127)] = make_float2(w, 0.f);
    }
    warp_fft128p(ln, lane);
    g_What2[(size_t)row * WSTRIDE + lane]      = ln[FIDX(lane)];
    g_What2[(size_t)row * WSTRIDE + lane + 32] = ln[FIDX(lane + 32)];
    if (lane == 0) g_What2[(size_t)row * WSTRIDE + 64] = ln[FIDX(64)];
}

// ---------------------------------------------------------------------------
// MEGA fused v8: 256 threads, 2 CTAs/SM. Scalar schoolbook mix with 1-deep W
// prefetch + register inverse FFT + fused combine.
// Grid split: blockIdx.z in {0,1} selects 4 of the 8 y-tiles (2048 blocks ->
// fills ~6.9 waves at 296 residency; kills the 4th-wave tail).
// smem: Gs 4160 f2 + Rs 7800 f2 = 95,680 B -> 2 CTAs/SM
// ---------------------------------------------------------------------------
__global__ __launch_bounds__(256, 2) void mega_kernel(const float* __restrict__ b_pos,
                                                      float* __restrict__ out) {
    extern __shared__ float2 sm[];
    float2* Gs = sm;                        // 4160 float2 (4y x 16k x 65f)
    float2* Rs = sm + 4160;                 // 7800 float2 (halo 4u x 30 x 65)
    const int dv = blockIdx.x, b = blockIdx.y;
    const int zt = blockIdx.z;              // 0..1 -> y-tiles zt*4 .. zt*4+3
    const int tid  = threadIdx.x;
    const int lane = tid & 31;
    const int wrp  = tid >> 5;              // 0..7
    const int kq = wrp & 3;
    const int fc = wrp >> 2;
    const int f  = fc * 32 + lane;          // 0..63
    const int bdv = b * 64 + dv;
    const int c_y = tid >> 4, c_k = tid & 15;
    const int k0 = wrp * 2, k1 = k0 + 1;
    const float add0 = b_pos[k0] + g_Lc[b * 1024 + k0 * 64 + dv];
    const float add1 = b_pos[k1] + g_Lc[b * 1024 + k1 * 64 + dv];
    const float sc = 1.0f / 128.0f;
    float* tile = (float*)Rs;               // alias: Rs[0..4095] f2, [16k][512px]

    for (int yt = zt * 4; yt < zt * 4 + 4; yt++) {
        const int y0 = yt * 8;
        __syncthreads();
        // ---- stage Rs halo rows y0-11 .. y0+18 (30 rows x 4u x 65f) ----
        for (int i = tid; i < 7800; i += 256) {
            int u   = i / 1950;
            int rem = i - u * 1950;
            int rr  = rem / 65;
            int ff  = rem - rr * 65;
            int y   = y0 + rr - 11;
            float2 val = make_float2(0.f, 0.f);
            if (y >= 0 && y < 64)
                val = g_Rhat[(((size_t)bdv * 4 + u) * 64 + y) * 65 + ff];
            Rs[i] = val;
        }
        __syncthreads();

        // ---- mix (scalar schoolbook, flattened loop, 1-deep W prefetch) ----
        float2 acc[8][4];
#pragma unroll
        for (int i = 0; i < 8; i++)
#pragma unroll
            for (int j = 0; j < 4; j++) acc[i][j] = make_float2(0.f, 0.f);

        {
            const float2* w0p = g_What2 + (size_t)((kq * 4 + 0) * 92) * WSTRIDE + f;
            const float2* w1p = g_What2 + (size_t)((kq * 4 + 1) * 92) * WSTRIDE + f;
            const float2* w2p = g_What2 + (size_t)((kq * 4 + 2) * 92) * WSTRIDE + f;
            const float2* w3p = g_What2 + (size_t)((kq * 4 + 3) * 92) * WSTRIDE + f;
            const float2* rp  = Rs + f;     // row cursor: (u*30 + dy)*65
            int dy = 0;
            float2 cw0 = w0p[0], cw1 = w1p[0], cw2 = w2p[0], cw3 = w3p[0];
#pragma unroll 1
            for (int it = 0; it < 92; it++) {
                // prefetch next iteration's W (padded table: it+1 <= 92 in-bounds)
                const int ni = (it + 1) * WSTRIDE;
                float2 nw0 = w0p[ni], nw1 = w1p[ni], nw2 = w2p[ni], nw3 = w3p[ni];
#pragma unroll
                for (int i = 0; i < 8; i++) {
                    float2 r = rp[i * 65];
                    acc[i][0].x = fmaf(r.x, cw0.x, acc[i][0].x);
                    acc[i][0].x = fmaf(-r.y, cw0.y, acc[i][0].x);
                    acc[i][0].y = fmaf(r.x, cw0.y, acc[i][0].y);
                    acc[i][0].y = fmaf(r.y, cw0.x, acc[i][0].y);
                    acc[i][1].x = fmaf(r.x, cw1.x, acc[i][1].x);
                    acc[i][1].x = fmaf(-r.y, cw1.y, acc[i][1].x);
                    acc[i][1].y = fmaf(r.x, cw1.y, acc[i][1].y);
                    acc[i][1].y = fmaf(r.y, cw1.x, acc[i][1].y);
                    acc[i][2].x = fmaf(r.x, cw2.x, acc[i][2].x);
                    acc[i][2].x = fmaf(-r.y, cw2.y, acc[i][2].x);
                    acc[i][2].y = fmaf(r.x, cw2.y, acc[i][2].y);
                    acc[i][2].y = fmaf(r.y, cw2.x, acc[i][2].y);
                    acc[i][3].x = fmaf(r.x, cw3.x, acc[i][3].x);
                    acc[i][3].x = fmaf(-r.y, cw3.y, acc[i][3].x);
                    acc[i][3].y = fmaf(r.x, cw3.y, acc[i][3].y);
                    acc[i][3].y = fmaf(r.y, cw3.x, acc[i][3].y);
                }
                cw0 = nw0; cw1 = nw1; cw2 = nw2; cw3 = nw3;
                rp += 65;
                if (++dy == 23) { dy = 0; rp += 7 * 65; }   // skip to next u block
            }
        }

        // ---- f = 64 Nyquist bin (threads 0..127), result kept in regs ----
        float2 ny = make_float2(0.f, 0.f);
        if (tid < 128) {
#pragma unroll 1
            for (int u = 0; u < 4; u++) {
                const float2* rptr = Rs + (u * 30 + c_y) * 65 + 64;
                const float2* wp = g_What2 + ((size_t)(c_k * 92 + u * 23)) * WSTRIDE + 64;
#pragma unroll
                for (int dy = 0; dy < 23; dy++) {
                    float2 r = rptr[dy * 65];
                    float2 w = wp[dy * WSTRIDE];
                    ny.x = fmaf(r.x, w.x, ny.x); ny.x = fmaf(-r.y, w.y, ny.x);
                    ny.y = fmaf(r.x, w.y, ny.y); ny.y = fmaf(r.y, w.x, ny.y);
                }
            }
        }

        // ---- two G halves: write 4 y rows -> register inverse FFT -> tile ----
#pragma unroll 1
        for (int half = 0; half < 2; half++) {
            __syncthreads();   // Gs free; Rs clobber OK (mix/ny done; tile alias)
#pragma unroll
            for (int i = 0; i < 4; i++)
#pragma unroll
                for (int j = 0; j < 4; j++)
                    Gs[(i * 16 + kq * 4 + j) * 65 + f] = acc[half * 4 + i][j];
            if (tid < 128 && (c_y >> 2) == half)
                Gs[((c_y & 3) * 16 + c_k) * 65 + 64] = ny;
            __syncthreads();   // Gs half complete

            // inverse: warp = k-pair, 4 lines, fully in registers
#pragma unroll 1
            for (int l = 0; l < 4; l++) {
                const float2* G0 = Gs + (l * 16 + k0) * 65;
                const float2* G1 = Gs + (l * 16 + k1) * 65;
                float2 v[4];
#pragma unroll
                for (int t = 0; t < 4; t++) {
                    int j = t * 32 + lane;
                    int ff = __brev((unsigned)j) >> 25;   // bit-reversed gather
                    float2 z;
                    if (ff <= 64) {
                        float2 a = G0[ff], c = G1[ff];
                        z = make_float2(a.x - c.y, a.y + c.x);
                    } else {
                        int g = 128 - ff;
                        float2 a = G0[g], c = G1[g];
                        z = make_float2(a.x + c.y, -a.y + c.x);
                    }
                    v[t] = make_float2(z.x, -z.y);        // conj for inverse
                }
                reg_fft128(v, lane);
                const int yl = half * 4 + l;
#pragma unroll
                for (int t = 0; t < 2; t++) {
                    int x = t * 32 + lane;
                    float2 o = v[t];
                    tile[k0 * 512 + yl * 64 + x] = o.x * sc + add0;
                    tile[k1 * 512 + yl * 64 + x] = -o.y * sc + add1;
                }
            }
        }
        __syncthreads();   // tile complete (both halves)

        // ---- combine: thread = px (two passes), 4 heads each ----
#pragma unroll
        for (int pp = 0; pp < 2; pp++) {
            const int px = tid + pp * 256;
            const int n = y0 * 64 + px;
            const float* qb = g_proj + (size_t)b * 384 * N_ + n;
#pragma unroll
            for (int h = 0; h < 4; h++) {
                float a = 0.f;
#pragma unroll
                for (int k = 0; k < 16; k++)
                    a = fmaf(qb[(size_t)(h * 16 + k) * N_], tile[k * 512 + px], a);
                out[((size_t)b * 256 + h * 64 + dv) * N_ + n] = a;
            }
        }
    }
}

// ---------------------------------------------------------------------------
extern "C" void kernel_launch(void* const* d_in, const int* in_sizes, int n_in,
                              void* d_out, int out_size) {
    const float* x     = (const float*)d_in[0];
    const float* w_q   = (const float*)d_in[1];
    const float* w_k   = (const float*)d_in[2];
    const float* w_v   = (const float*)d_in[3];
    const float* gq    = (const float*)d_in[4];
    const float* bq    = (const float*)d_in[5];
    const float* mq    = (const float*)d_in[6];
    const float* vq    = (const float*)d_in[7];
    const float* gv    = (const float*)d_in[8];
    const float* bv    = (const float*)d_in[9];
    const float* mv    = (const float*)d_in[10];
    const float* vvar  = (const float*)d_in[11];
    const float* w_pos = (const float*)d_in[12];
    const float* b_pos = (const float*)d_in[13];
    float* out = (float*)d_out;

    const int MEGA_SMEM = (4160 + 7800) * sizeof(float2);   // 95,680 B -> 2 CTAs/SM
    cudaFuncSetAttribute(mega_kernel, cudaFuncAttributeMaxDynamicSharedMemorySize, MEGA_SMEM);

    twiddle_kernel<<<1, 64>>>();
    fold_kernel<<<2, 256>>>(w_q, w_k, w_v, gq, bq, mq, vq, gv, bv, mv, vvar);
    proj_gemm_kernel<<<dim3(32, 6, 16), 256>>>(x);
    rhat_kernel<<<16384, 256>>>();        // 4th launch -> ncu capture slot
    softmax_kernel<<<1024, 256>>>();
    lc_partial_kernel<<<dim3(8, 4, 16), 256>>>();
    lc_reduce_kernel<<<16, 1024>>>();
    what_kernel<<<184, 256>>>(w_pos);
    mega_kernel<<<dim3(64, 16, 2), 256, MEGA_SMEM>>>(b_pos, out);
}